// round 2
// baseline (speedup 1.0000x reference)
#include <cuda_runtime.h>
#include <math_constants.h>

// Problem constants (CodebookEMA): z [32,256,32,32], embedding [1024,256]
#define TM   128   // tokens per block (argmin kernel)
#define TKK  128   // codes per k-tile
#define DCH  16    // d-chunk
constexpr int D    = 256;
constexpr int K    = 1024;
constexpr int HW   = 1024;   // 32*32
constexpr int NTOK = 32768;  // 32*32*32

// -------- scratch (no allocations allowed) --------
__device__ int   g_idx[NTOK];
__device__ float g_counts[K];
__device__ float g_dw[K * D];
__device__ float g_loss;
__device__ float g_eh[K];      // 0.5*||e_k||^2

// -------- packed fp32x2 helpers (exact: two independent IEEE fp32 FMAs) ----
__device__ __forceinline__ unsigned long long pk2(float lo, float hi) {
    unsigned long long r;
    asm("mov.b64 %0, {%1, %2};" : "=l"(r)
        : "r"(__float_as_uint(lo)), "r"(__float_as_uint(hi)));
    return r;
}
__device__ __forceinline__ void upk2(unsigned long long v, float& lo, float& hi) {
    unsigned int a, b;
    asm("mov.b64 {%0, %1}, %2;" : "=r"(a), "=r"(b) : "l"(v));
    lo = __uint_as_float(a); hi = __uint_as_float(b);
}
__device__ __forceinline__ void fma2(unsigned long long& d,
                                     unsigned long long a, unsigned long long b) {
    asm("fma.rn.f32x2 %0, %1, %2, %0;" : "+l"(d) : "l"(a), "l"(b));
}

// -------- zero scratch (must run every launch: graph replays) --------
__global__ void k_zero() {
    int i = blockIdx.x * blockDim.x + threadIdx.x;
    if (i < K * D) g_dw[i] = 0.0f;
    if (i < K)     g_counts[i] = 0.0f;
    if (i == 0)    g_loss = 0.0f;
}

// -------- 0.5*||e_k||^2, one warp per code --------
__global__ void k_eh(const float* __restrict__ emb) {
    int w    = (blockIdx.x * blockDim.x + threadIdx.x) >> 5;
    int lane = threadIdx.x & 31;
    if (w >= K) return;
    const float4* r = reinterpret_cast<const float4*>(emb + (size_t)w * D) + lane * 2;
    float4 a = r[0], b = r[1];
    float s = a.x*a.x + a.y*a.y + a.z*a.z + a.w*a.w
            + b.x*b.x + b.y*b.y + b.z*b.z + b.w*b.w;
    #pragma unroll
    for (int o = 16; o > 0; o >>= 1) s += __shfl_xor_sync(0xffffffffu, s, o);
    if (lane == 0) g_eh[w] = 0.5f * s;
}

// -------- fused distance-GEMM + argmin --------
// dist'(n,k) = 0.5*||e_k||^2 - z_n . e_k   (same argmin as ||z||^2+||e||^2-2 z.e)
// Block: 128 tokens, loops 8 k-tiles x 16 d-chunks. z tile staged in smem once.
__global__ __launch_bounds__(256, 1)
void k_argmin(const float* __restrict__ z, const float* __restrict__ emb,
              float* __restrict__ out_idx) {
    extern __shared__ float sm[];
    float* As = sm;                       // [D][TM]   d-major, 128 KB
    float* Bs = As + D * TM;              // [DCH][TKK]
    float* Eh = Bs + DCH * TKK;           // [K]
    float* Rv = Eh + K;                   // [16][TM]
    int*   Ri = reinterpret_cast<int*>(Rv + 16 * TM);

    const int tid  = threadIdx.x;
    const int tok0 = blockIdx.x * TM;
    const int b    = tok0 >> 10;
    const int toff = tok0 & 1023;
    const float* zb = z + (size_t)b * D * HW + toff;

    for (int i = tid; i < K; i += 256) Eh[i] = g_eh[i];

    {   // stage z tile: As[d][t], coalesced float4 per (d, 32-thread group)
        int t4 = tid & 31;
        int dr = tid >> 5;
        #pragma unroll 4
        for (int d = dr; d < D; d += 8) {
            float4 v = *reinterpret_cast<const float4*>(zb + (size_t)d * HW + (t4 << 2));
            *reinterpret_cast<float4*>(As + d * TM + (t4 << 2)) = v;
        }
    }

    const int tr = tid >> 4;   // token group: rows tr*8 .. tr*8+7
    const int tc = tid & 15;   // code lane: codes tc + 16*j (j=0..7) within tile

    float minv[8]; int mini[8];
    #pragma unroll
    for (int i = 0; i < 8; i++) { minv[i] = CUDART_INF_F; mini[i] = 0; }

    // B prefetch regs: each thread loads 8 consecutive d of one code
    const int pcode = tid >> 1;
    const int pdd   = (tid & 1) * 8;
    float4 pf0, pf1;
    const int NCH = (K / TKK) * (D / DCH);   // 128

    {   // prefetch chunk 0
        const float* src = emb + (size_t)pcode * D + pdd;   // kt=0, dc=0
        pf0 = *reinterpret_cast<const float4*>(src);
        pf1 = *reinterpret_cast<const float4*>(src + 4);
    }

    unsigned long long acc[8][4];

    for (int m = 0; m < NCH; m++) {
        if ((m & 15) == 0) {
            #pragma unroll
            for (int i = 0; i < 8; i++)
                #pragma unroll
                for (int jj = 0; jj < 4; jj++) acc[i][jj] = 0ull;
        }
        __syncthreads();
        {   // commit prefetched B chunk to smem (d-major)
            Bs[(pdd + 0) * TKK + pcode] = pf0.x;
            Bs[(pdd + 1) * TKK + pcode] = pf0.y;
            Bs[(pdd + 2) * TKK + pcode] = pf0.z;
            Bs[(pdd + 3) * TKK + pcode] = pf0.w;
            Bs[(pdd + 4) * TKK + pcode] = pf1.x;
            Bs[(pdd + 5) * TKK + pcode] = pf1.y;
            Bs[(pdd + 6) * TKK + pcode] = pf1.z;
            Bs[(pdd + 7) * TKK + pcode] = pf1.w;
        }
        __syncthreads();
        if (m + 1 < NCH) {   // prefetch next chunk while computing
            int kt = ((m + 1) >> 4) * TKK;
            int dc = ((m + 1) & 15) * DCH;
            const float* src = emb + (size_t)(kt + pcode) * D + dc + pdd;
            pf0 = *reinterpret_cast<const float4*>(src);
            pf1 = *reinterpret_cast<const float4*>(src + 4);
        }

        const int dbase = (m & 15) * DCH;
        #pragma unroll
        for (int dd = 0; dd < DCH; dd++) {
            const float* ar = As + (dbase + dd) * TM + tr * 8;
            const float* br = Bs + dd * TKK + tc;
            float4 av0 = *reinterpret_cast<const float4*>(ar);
            float4 av1 = *reinterpret_cast<const float4*>(ar + 4);
            unsigned long long bv[4];
            #pragma unroll
            for (int jj = 0; jj < 4; jj++)
                bv[jj] = pk2(br[32 * jj], br[32 * jj + 16]);
            float aa[8] = {av0.x, av0.y, av0.z, av0.w, av1.x, av1.y, av1.z, av1.w};
            #pragma unroll
            for (int i = 0; i < 8; i++) {
                unsigned long long ap = pk2(aa[i], aa[i]);
                #pragma unroll
                for (int jj = 0; jj < 4; jj++) fma2(acc[i][jj], ap, bv[jj]);
            }
        }

        if ((m & 15) == 15) {   // k-tile epilogue: fold into running argmin
            int kt = (m >> 4) * TKK;
            #pragma unroll
            for (int i = 0; i < 8; i++) {
                #pragma unroll
                for (int jj = 0; jj < 4; jj++) {
                    float lo, hi; upk2(acc[i][jj], lo, hi);
                    int   c0 = kt + tc + 32 * jj;
                    float d0 = Eh[c0]      - lo;
                    float d1 = Eh[c0 + 16] - hi;
                    if (d0 < minv[i]) { minv[i] = d0; mini[i] = c0; }
                    if (d1 < minv[i]) { minv[i] = d1; mini[i] = c0 + 16; }
                }
            }
        }
    }

    __syncthreads();
    #pragma unroll
    for (int i = 0; i < 8; i++) {
        int t = tr * 8 + i;
        Rv[tc * TM + t] = minv[i];
        Ri[tc * TM + t] = mini[i];
    }
    __syncthreads();
    if (tid < TM) {
        float bv = Rv[tid]; int bi = Ri[tid];
        #pragma unroll
        for (int c = 1; c < 16; c++) {
            float v = Rv[c * TM + tid];
            if (v < bv) { bv = v; bi = Ri[c * TM + tid]; }
        }
        int n = tok0 + tid;
        g_idx[n] = bi;
        out_idx[n] = (float)bi;
        atomicAdd(&g_counts[bi], 1.0f);
    }
}

// -------- gather z_q + loss + dw scatter --------
__global__ __launch_bounds__(256)
void k_scatter(const float* __restrict__ z, const float* __restrict__ emb,
               float* __restrict__ out_zq) {
    __shared__ int   sIdx[TM];
    __shared__ float red[256];
    const int tid  = threadIdx.x;
    const int tok0 = blockIdx.x * TM;
    const int b    = tok0 >> 10;
    const int toff = tok0 & 1023;
    if (tid < TM) sIdx[tid] = g_idx[tok0 + tid];
    __syncthreads();

    const float* zb = z      + (size_t)b * D * HW + toff;
    float*       qb = out_zq + (size_t)b * D * HW + toff;
    const int tk = tid & 127;
    const int ch = tid >> 7;    // 0/1
    const int k  = sIdx[tk];
    const float* er  = emb  + (size_t)k * D;
    float*       dwr = g_dw + (size_t)k * D;

    float ls = 0.0f;
    #pragma unroll 4
    for (int c0 = 0; c0 < D; c0 += 2) {
        int   c  = c0 + ch;
        float zv = zb[(size_t)c * HW + tk];
        float ev = er[c];
        float df = ev - zv;
        qb[(size_t)c * HW + tk] = zv + df;   // straight-through: zp + (z_q - zp)
        ls += df * df;
        atomicAdd(&dwr[c], zv);              // segment_sum of zf
    }
    red[tid] = ls;
    __syncthreads();
    #pragma unroll
    for (int s = 128; s > 0; s >>= 1) {
        if (tid < s) red[tid] += red[tid + s];
        __syncthreads();
    }
    if (tid == 0) atomicAdd(&g_loss, red[0]);
}

// -------- cluster-size EMA + Laplace smoothing (one block) --------
__global__ void k_cs(const float* __restrict__ ecs, float* __restrict__ out_cs) {
    __shared__ float sred[K];
    int k = threadIdx.x;
    float cr = 0.99f * ecs[k] + 0.01f * g_counts[k];
    sred[k] = cr;
    __syncthreads();
    #pragma unroll
    for (int s = K / 2; s > 0; s >>= 1) {
        if (k < s) sred[k] += sred[k + s];
        __syncthreads();
    }
    float n = sred[0];
    out_cs[k] = (cr + 1e-5f) / (n + (float)K * 1e-5f) * n;
}

// -------- new_ema_w + new_embedding --------
__global__ void k_emb(const float* __restrict__ ema_w, const float* __restrict__ cs,
                      float* __restrict__ out_emaw, float* __restrict__ out_emb) {
    int i = blockIdx.x * blockDim.x + threadIdx.x;
    if (i < K * D) {
        float w = 0.99f * ema_w[i] + 0.01f * g_dw[i];
        out_emaw[i] = w;
        out_emb[i]  = w / cs[i >> 8];
    }
}

__global__ void k_loss(float* __restrict__ out_loss) {
    if (threadIdx.x == 0)
        out_loss[0] = 0.25f * g_loss / (float)((size_t)NTOK * D);
}

extern "C" void kernel_launch(void* const* d_in, const int* in_sizes, int n_in,
                              void* d_out, int out_size) {
    const float* z    = (const float*)d_in[0];   // [32,256,32,32]
    const float* emb  = (const float*)d_in[1];   // [1024,256]
    const float* ecs  = (const float*)d_in[2];   // [1024]
    const float* emaw = (const float*)d_in[3];   // [1024,256]
    float* out = (float*)d_out;

    // output layout: z_q | idx | loss | new_embedding | cs | new_ema_w
    const size_t o_idx  = (size_t)NTOK * D;      // 8388608
    const size_t o_loss = o_idx + NTOK;
    const size_t o_emb  = o_loss + 1;
    const size_t o_cs   = o_emb + (size_t)K * D;
    const size_t o_emaw = o_cs + K;

    const int SMEM_BYTES = (D * TM + DCH * TKK + K + 2 * 16 * TM) * 4;  // ~156 KB
    cudaFuncSetAttribute(k_argmin, cudaFuncAttributeMaxDynamicSharedMemorySize,
                         SMEM_BYTES);

    k_zero   <<<(K * D + 255) / 256, 256>>>();
    k_eh     <<<K / 8, 256>>>(emb);
    k_argmin <<<NTOK / TM, 256, SMEM_BYTES>>>(z, emb, out + o_idx);
    k_scatter<<<NTOK / TM, 256>>>(z, emb, out);
    k_cs     <<<1, K>>>(ecs, out + o_cs);
    k_emb    <<<(K * D + 255) / 256, 256>>>(emaw, out + o_cs,
                                            out + o_emaw, out + o_emb);
    k_loss   <<<1, 32>>>(out + o_loss);
}

// round 3
// speedup vs baseline: 1.1658x; 1.1658x over previous
#include <cuda_runtime.h>
#include <math_constants.h>

// Problem constants (CodebookEMA): z [32,256,32,32], embedding [1024,256]
#define TM   128   // tokens per block
#define TKK  128   // codes per k-tile
#define DCH  16    // d-chunk rows
constexpr int D    = 256;
constexpr int K    = 1024;
constexpr int HW   = 1024;   // 32*32
constexpr int NTOK = 32768;  // 32*32*32
constexpr int NCH  = (K / TKK) * (D / DCH);   // 128 chunks

// -------- scratch (no allocations allowed; zero-init, restored by consumers) --
__device__ float g_counts[K];
__device__ float g_dw[K * D];
__device__ float g_loss;
__device__ float g_eh[K];      // 0.5*||e_k||^2

// -------- packed fp32x2 helpers (exact: two independent IEEE fp32 FMAs) ----
__device__ __forceinline__ unsigned long long pk2(float lo, float hi) {
    unsigned long long r;
    asm("mov.b64 %0, {%1, %2};" : "=l"(r)
        : "r"(__float_as_uint(lo)), "r"(__float_as_uint(hi)));
    return r;
}
__device__ __forceinline__ void upk2(unsigned long long v, float& lo, float& hi) {
    unsigned int a, b;
    asm("mov.b64 {%0, %1}, %2;" : "=r"(a), "=r"(b) : "l"(v));
    lo = __uint_as_float(a); hi = __uint_as_float(b);
}
__device__ __forceinline__ void fma2(unsigned long long& d,
                                     unsigned long long a, unsigned long long b) {
    asm("fma.rn.f32x2 %0, %1, %2, %0;" : "+l"(d) : "l"(a), "l"(b));
}

// -------- 0.5*||e_k||^2, one warp per code --------
__global__ void k_eh(const float* __restrict__ emb) {
    int w    = (blockIdx.x * blockDim.x + threadIdx.x) >> 5;
    int lane = threadIdx.x & 31;
    if (w >= K) return;
    const float4* r = reinterpret_cast<const float4*>(emb + (size_t)w * D) + lane * 2;
    float4 a = r[0], b = r[1];
    float s = a.x*a.x + a.y*a.y + a.z*a.z + a.w*a.w
            + b.x*b.x + b.y*b.y + b.z*b.z + b.w*b.w;
    #pragma unroll
    for (int o = 16; o > 0; o >>= 1) s += __shfl_xor_sync(0xffffffffu, s, o);
    if (lane == 0) g_eh[w] = 0.5f * s;
}

// -------- fused distance-GEMM + argmin + gather/scatter epilogue --------
// dist'(n,k) = 0.5*||e_k||^2 - z_n . e_k   (same argmin as full formula)
__global__ __launch_bounds__(256, 1)
void k_argmin(const float* __restrict__ z, const float* __restrict__ emb,
              float* __restrict__ out_idx, float* __restrict__ out_zq) {
    extern __shared__ float sm[];
    float* As  = sm;                      // [D][TM]      128 KB, z tile d-major
    float* Bs  = As + D * TM;             // 2x [DCH][TKK] double-buffered, 16 KB
    float* Eh  = Bs + 2 * DCH * TKK;      // [K]
    float* Rv  = Eh + K;                  // [16][TM]
    int*   Ri  = reinterpret_cast<int*>(Rv + 16 * TM);

    const int tid  = threadIdx.x;
    const int tok0 = blockIdx.x * TM;
    const int b    = tok0 >> 10;
    const int toff = tok0 & 1023;
    const float* zb = z + (size_t)b * D * HW + toff;

    for (int i = tid; i < K; i += 256) Eh[i] = g_eh[i];

    {   // stage z tile: As[d][t], coalesced float4
        int t4 = tid & 31;
        int dr = tid >> 5;
        #pragma unroll 4
        for (int d = dr; d < D; d += 8) {
            float4 v = *reinterpret_cast<const float4*>(zb + (size_t)d * HW + (t4 << 2));
            *reinterpret_cast<float4*>(As + d * TM + (t4 << 2)) = v;
        }
    }

    const int tr  = tid >> 4;      // token group: rows tr*8 .. tr*8+7
    const int tc  = tid & 15;      // code lane:  pairs (2tc+32j, 2tc+32j+1)
    const int tc2 = tc * 2;

    float minv[8]; int mini[8];
    #pragma unroll
    for (int i = 0; i < 8; i++) { minv[i] = CUDART_INF_F; mini[i] = 0; }

    // B prefetch regs: each thread loads 8 consecutive d of one code
    const int pcode = tid >> 1;
    const int pdd   = (tid & 1) * 8;
    float4 pf0, pf1;

    auto chunk_src = [&](int q) -> const float* {
        int kt = (q >> 4) * TKK;
        int dc = (q & 15) * DCH;
        return emb + (size_t)(kt + pcode) * D + dc + pdd;
    };
    auto commit = [&](float* Bdst) {
        Bdst[(pdd + 0) * TKK + pcode] = pf0.x;
        Bdst[(pdd + 1) * TKK + pcode] = pf0.y;
        Bdst[(pdd + 2) * TKK + pcode] = pf0.z;
        Bdst[(pdd + 3) * TKK + pcode] = pf0.w;
        Bdst[(pdd + 4) * TKK + pcode] = pf1.x;
        Bdst[(pdd + 5) * TKK + pcode] = pf1.y;
        Bdst[(pdd + 6) * TKK + pcode] = pf1.z;
        Bdst[(pdd + 7) * TKK + pcode] = pf1.w;
    };

    // chunk 0 -> buf0, chunk 1 in flight
    { const float* s0 = chunk_src(0);
      pf0 = *reinterpret_cast<const float4*>(s0);
      pf1 = *reinterpret_cast<const float4*>(s0 + 4); }
    commit(Bs);
    { const float* s1 = chunk_src(1);
      pf0 = *reinterpret_cast<const float4*>(s1);
      pf1 = *reinterpret_cast<const float4*>(s1 + 4); }
    __syncthreads();   // As, Eh, Bs[0] ready

    unsigned long long acc[8][4];

    for (int m = 0; m < NCH; m++) {
        const float* Bc = Bs + (m & 1) * (DCH * TKK);
        if ((m & 15) == 0) {
            #pragma unroll
            for (int i = 0; i < 8; i++)
                #pragma unroll
                for (int jj = 0; jj < 4; jj++) acc[i][jj] = 0ull;
        }
        if (m + 1 < NCH) commit(Bs + ((m + 1) & 1) * (DCH * TKK));
        if (m + 2 < NCH) {
            const float* sn = chunk_src(m + 2);
            pf0 = *reinterpret_cast<const float4*>(sn);
            pf1 = *reinterpret_cast<const float4*>(sn + 4);
        }

        #pragma unroll
        for (int dd = 0; dd < DCH; dd++) {
            const float* ar = As + (((m & 15) * DCH) + dd) * TM + tr * 8;
            const float* br = Bc + dd * TKK + tc2;
            float4 av0 = *reinterpret_cast<const float4*>(ar);
            float4 av1 = *reinterpret_cast<const float4*>(ar + 4);
            unsigned long long bv[4];
            #pragma unroll
            for (int jj = 0; jj < 4; jj++)
                bv[jj] = *reinterpret_cast<const unsigned long long*>(br + 32 * jj);
            float aa[8] = {av0.x, av0.y, av0.z, av0.w, av1.x, av1.y, av1.z, av1.w};
            #pragma unroll
            for (int i = 0; i < 8; i++) {
                unsigned long long ap = pk2(aa[i], aa[i]);
                #pragma unroll
                for (int jj = 0; jj < 4; jj++) fma2(acc[i][jj], ap, bv[jj]);
            }
        }

        if ((m & 15) == 15) {   // k-tile epilogue: fold into running argmin
            int kt = (m >> 4) * TKK;
            #pragma unroll
            for (int i = 0; i < 8; i++) {
                #pragma unroll
                for (int jj = 0; jj < 4; jj++) {
                    float lo, hi; upk2(acc[i][jj], lo, hi);
                    int   c0 = kt + tc2 + 32 * jj;
                    float d0 = Eh[c0]     - lo;
                    float d1 = Eh[c0 + 1] - hi;
                    if (d0 < minv[i]) { minv[i] = d0; mini[i] = c0; }
                    if (d1 < minv[i]) { minv[i] = d1; mini[i] = c0 + 1; }
                }
            }
        }
        __syncthreads();
    }

    // cross-thread argmin (16 code-lanes per token)
    #pragma unroll
    for (int i = 0; i < 8; i++) {
        int t = tr * 8 + i;
        Rv[tc * TM + t] = minv[i];
        Ri[tc * TM + t] = mini[i];
    }
    __syncthreads();
    if (tid < TM) {
        float bv = Rv[tid]; int bi = Ri[tid];
        #pragma unroll
        for (int c = 1; c < 16; c++) {
            float v = Rv[c * TM + tid];
            if (v < bv) { bv = v; bi = Ri[c * TM + tid]; }
        }
        int n = tok0 + tid;
        out_idx[n] = (float)bi;
        atomicAdd(&g_counts[bi], 1.0f);
        Ri[tid] = bi;          // broadcast final index (own slot, already read)
    }
    __syncthreads();

    // ---- fused scatter epilogue: z_q, loss, dw (z read from smem) ----
    const int tk  = tid & 127;
    const int chh = tid >> 7;
    const int k   = Ri[tk];
    const float* er  = emb + (size_t)k * D;
    float*       dwr = g_dw + (size_t)k * D;
    float*       qb  = out_zq + (size_t)b * D * HW + toff;

    float ls = 0.0f;
    #pragma unroll 4
    for (int c0 = 0; c0 < D; c0 += 2) {
        int   c  = c0 + chh;
        float zv = As[c * TM + tk];
        float ev = er[c];
        float df = ev - zv;
        qb[(size_t)c * HW + tk] = zv + df;   // straight-through: zp + (z_q - zp)
        ls += df * df;
        atomicAdd(&dwr[c], zv);              // segment_sum of zf
    }
    Rv[tid] = ls;
    __syncthreads();
    #pragma unroll
    for (int s = 128; s > 0; s >>= 1) {
        if (tid < s) Rv[tid] += Rv[tid + s];
        __syncthreads();
    }
    if (tid == 0) atomicAdd(&g_loss, Rv[0]);
}

// -------- cluster-size EMA + Laplace smoothing; consumes+zeros g_counts -----
__global__ void k_cs(const float* __restrict__ ecs, float* __restrict__ out_cs) {
    __shared__ float sred[K];
    int k = threadIdx.x;
    float cr = 0.99f * ecs[k] + 0.01f * g_counts[k];
    g_counts[k] = 0.0f;                     // restore zeroed state for next replay
    sred[k] = cr;
    __syncthreads();
    #pragma unroll
    for (int s = K / 2; s > 0; s >>= 1) {
        if (k < s) sred[k] += sred[k + s];
        __syncthreads();
    }
    float n = sred[0];
    out_cs[k] = (cr + 1e-5f) / (n + (float)K * 1e-5f) * n;
}

// -------- new_ema_w + new_embedding; consumes+zeros g_dw --------
__global__ void k_emb(const float* __restrict__ ema_w, const float* __restrict__ cs,
                      float* __restrict__ out_emaw, float* __restrict__ out_emb) {
    int i = blockIdx.x * blockDim.x + threadIdx.x;
    if (i < K * D) {
        float w = 0.99f * ema_w[i] + 0.01f * g_dw[i];
        g_dw[i] = 0.0f;                     // restore zeroed state
        out_emaw[i] = w;
        out_emb[i]  = w / cs[i >> 8];
    }
}

__global__ void k_loss(float* __restrict__ out_loss) {
    if (threadIdx.x == 0) {
        out_loss[0] = 0.25f * g_loss / (float)((size_t)NTOK * D);
        g_loss = 0.0f;                      // restore zeroed state
    }
}

extern "C" void kernel_launch(void* const* d_in, const int* in_sizes, int n_in,
                              void* d_out, int out_size) {
    const float* z    = (const float*)d_in[0];   // [32,256,32,32]
    const float* emb  = (const float*)d_in[1];   // [1024,256]
    const float* ecs  = (const float*)d_in[2];   // [1024]
    const float* emaw = (const float*)d_in[3];   // [1024,256]
    float* out = (float*)d_out;

    // output layout: z_q | idx | loss | new_embedding | cs | new_ema_w
    const size_t o_idx  = (size_t)NTOK * D;      // 8388608
    const size_t o_loss = o_idx + NTOK;
    const size_t o_emb  = o_loss + 1;
    const size_t o_cs   = o_emb + (size_t)K * D;
    const size_t o_emaw = o_cs + K;

    const int SMEM_BYTES =
        (D * TM + 2 * DCH * TKK + K + 2 * 16 * TM) * 4;   // ~164 KB
    cudaFuncSetAttribute(k_argmin, cudaFuncAttributeMaxDynamicSharedMemorySize,
                         SMEM_BYTES);

    k_eh     <<<K / 8, 256>>>(emb);
    k_argmin <<<NTOK / TM, 256, SMEM_BYTES>>>(z, emb, out + o_idx, out);
    k_cs     <<<1, K>>>(ecs, out + o_cs);
    k_emb    <<<(K * D + 255) / 256, 256>>>(emaw, out + o_cs,
                                            out + o_emaw, out + o_emb);
    k_loss   <<<1, 32>>>(out + o_loss);
}

// round 8
// speedup vs baseline: 1.8450x; 1.5826x over previous
#include <cuda_runtime.h>
#include <cuda_fp16.h>
#include <math_constants.h>
#include <cstdint>

// Problem: z [32,256,32,32], embedding [1024,256]
constexpr int D    = 256;
constexpr int K    = 1024;
constexpr int HW   = 1024;
constexpr int NTOK = 32768;
constexpr int TM   = 128;        // tokens per CTA
constexpr int NB   = 32;         // codes per chunk
constexpr int NCHK = K / NB;     // 32

// smem offsets in u32 units
constexpr int S_AHI = 0;         // [128 tok][128 kp] u32(half2)  64KB
constexpr int S_ALO = 16384;
constexpr int S_B   = 32768;     // 2 bufs x (hi 4096 + lo 4096)  64KB
constexpr int S_EH  = 49152;     // 1024 f32
constexpr int S_RI  = 50176;     // 128 i32
constexpr int S_RED = 50304;     // 256 f32
constexpr int SMEM_U32   = 50560;
constexpr int SMEM_BYTES = SMEM_U32 * 4;   // 202240

// ---- device scratch (static; zero-init, restored by consumers each replay) --
__device__ uint32_t g_Ahi[NTOK * 128];   // half2-packed hi of z, token-major
__device__ uint32_t g_Alo[NTOK * 128];
__device__ uint32_t g_Bhi[K * 128];      // half2-packed hi of emb
__device__ uint32_t g_Blo[K * 128];
__device__ float g_counts[K];
__device__ float g_dw[K * D];
__device__ float g_loss;
__device__ float g_eh[K];                // 0.5*||e_k||^2

// ---------------- helpers ----------------
__device__ __forceinline__ uint32_t smaddr(const void* p) {
    uint32_t a;
    asm("{ .reg .u64 t; cvta.to.shared.u64 t, %1; cvt.u32.u64 %0, t; }"
        : "=r"(a) : "l"(p));
    return a;
}
__device__ __forceinline__ void cp16(uint32_t s, const void* g) {
    asm volatile("cp.async.cg.shared.global [%0], [%1], 16;" :: "r"(s), "l"(g));
}
__device__ __forceinline__ void cp_commit_wait() {
    asm volatile("cp.async.commit_group;" ::: "memory");
    asm volatile("cp.async.wait_group 0;" ::: "memory");
}
__device__ __forceinline__ void mma_f16(float* c, const uint32_t* a,
                                        const uint32_t* b) {
    asm volatile("mma.sync.aligned.m16n8k16.row.col.f32.f16.f16.f32 "
        "{%0,%1,%2,%3},{%4,%5,%6,%7},{%8,%9},{%0,%1,%2,%3};"
        : "+f"(c[0]), "+f"(c[1]), "+f"(c[2]), "+f"(c[3])
        : "r"(a[0]), "r"(a[1]), "r"(a[2]), "r"(a[3]), "r"(b[0]), "r"(b[1]));
}
__device__ __forceinline__ uint32_t packsplit(float v0, float v1, uint32_t& lo) {
    __half h0 = __float2half_rn(v0), h1 = __float2half_rn(v1);
    __half l0 = __float2half_rn(v0 - __half2float(h0));
    __half l1 = __float2half_rn(v1 - __half2float(h1));
    __half2 H = __halves2half2(h0, h1), L = __halves2half2(l0, l1);
    lo = *reinterpret_cast<uint32_t*>(&L);
    return *reinterpret_cast<uint32_t*>(&H);
}

// ---------------- split z -> fp16 hi/lo, token-major ----------------
__global__ void k_split_z(const float* __restrict__ z) {
    const int tid  = threadIdx.x;
    const int blk  = blockIdx.x;                 // 128 blocks x 256 tokens
    const int b    = blk >> 2;
    const int toff = ((blk & 3) << 8) + tid;
    const int tok  = (b << 10) + toff;
    const float* zp = z + (size_t)b * D * HW + toff;
    uint4* Oh = reinterpret_cast<uint4*>(g_Ahi) + (size_t)tok * 32;
    uint4* Ol = reinterpret_cast<uint4*>(g_Alo) + (size_t)tok * 32;
    for (int g = 0; g < 32; g++) {               // FULL row: 32 uint4 = 128 u32 = 256 d
        uint32_t hv[4], lv[4];
        #pragma unroll
        for (int q = 0; q < 4; q++) {
            int d0 = (g * 4 + q) * 2;
            float v0 = zp[(size_t)d0 * HW];
            float v1 = zp[(size_t)(d0 + 1) * HW];
            hv[q] = packsplit(v0, v1, lv[q]);
        }
        Oh[g] = make_uint4(hv[0], hv[1], hv[2], hv[3]);
        Ol[g] = make_uint4(lv[0], lv[1], lv[2], lv[3]);
    }
}

// ---------------- split emb -> fp16 hi/lo + 0.5*||e||^2 ----------------
__global__ void k_split_emb(const float* __restrict__ emb) {
    const int wid  = threadIdx.x >> 5, lane = threadIdx.x & 31;
    const int code = blockIdx.x * 8 + wid;
    const float4* r = reinterpret_cast<const float4*>(emb + (size_t)code * D)
                    + lane * 2;
    float4 a = r[0], bq = r[1];
    float v[8] = {a.x, a.y, a.z, a.w, bq.x, bq.y, bq.z, bq.w};
    float s = 0.0f;
    uint32_t hv[4], lv[4];
    #pragma unroll
    for (int q = 0; q < 4; q++) {
        s += v[2*q] * v[2*q] + v[2*q+1] * v[2*q+1];
        hv[q] = packsplit(v[2*q], v[2*q+1], lv[q]);
    }
    reinterpret_cast<uint4*>(g_Bhi)[(size_t)code * 32 + lane] =
        make_uint4(hv[0], hv[1], hv[2], hv[3]);
    reinterpret_cast<uint4*>(g_Blo)[(size_t)code * 32 + lane] =
        make_uint4(lv[0], lv[1], lv[2], lv[3]);
    #pragma unroll
    for (int o = 16; o > 0; o >>= 1) s += __shfl_xor_sync(0xffffffffu, s, o);
    if (lane == 0) g_eh[code] = 0.5f * s;
}

// -------- main: HMMA fp16x2 3-product GEMM + argmin + scatter --------
__global__ __launch_bounds__(256, 1)
void k_argmin(const float* __restrict__ emb,
              float* __restrict__ out_idx, float* __restrict__ out_zq) {
    extern __shared__ uint32_t sm[];
    const uint32_t sbase = smaddr(sm);
    float* Eh  = reinterpret_cast<float*>(sm + S_EH);
    int*   Ri  = reinterpret_cast<int*>(sm + S_RI);
    float* RED = reinterpret_cast<float*>(sm + S_RED);

    const int tid  = threadIdx.x;
    const int wid  = tid >> 5;
    const int lane = tid & 31;
    const int tok0 = blockIdx.x * TM;

    // ---- prologue: stage A (hi/lo, swizzled) + B chunk0 + Eh ----
    #pragma unroll 4
    for (int i = 0; i < 32; i++) {
        int grp = tid + 256 * i;
        int hl = grp >> 12, r = grp & 4095, row = r >> 5, g4 = (r & 31) << 2;
        const uint32_t* src = (hl ? g_Alo : g_Ahi)
                            + (size_t)(tok0 + row) * 128 + g4;
        uint32_t dst = sbase
            + ((hl ? S_ALO : S_AHI) + row * 128 + (g4 ^ ((row & 7) << 2))) * 4;
        cp16(dst, src);
    }
    #pragma unroll
    for (int i = 0; i < 8; i++) {
        int grp = tid + 256 * i;
        int hl = grp >> 10, r = grp & 1023, row = r >> 5, g4 = (r & 31) << 2;
        const uint32_t* src = (hl ? g_Blo : g_Bhi) + (size_t)row * 128 + g4;
        uint32_t dst = sbase
            + (S_B + hl * 4096 + row * 128 + (g4 ^ ((row & 7) << 2))) * 4;
        cp16(dst, src);
    }
    for (int i = tid; i < K; i += 256) Eh[i] = g_eh[i];
    cp_commit_wait();
    __syncthreads();

    const int g  = lane >> 2;       // row group 0..7
    const int tg = lane & 3;        // thread-in-group
    const int xr = g << 2;          // frag-load swizzle term
    const uint32_t* sAh = sm + S_AHI;
    const uint32_t* sAl = sm + S_ALO;
    const int baseA  = (wid * 32 + g) * 128;   // valid for wid<4
    const int baseB0 = g * 128;

    float minv[4] = {CUDART_INF_F, CUDART_INF_F, CUDART_INF_F, CUDART_INF_F};
    int   mini[4] = {0, 0, 0, 0};

    for (int c = 0; c < NCHK; c++) {
        if (wid < 4) {
            float acc[2][4][4];
            #pragma unroll
            for (int mt = 0; mt < 2; mt++)
                #pragma unroll
                for (int nt = 0; nt < 4; nt++)
                    #pragma unroll
                    for (int e = 0; e < 4; e++) acc[mt][nt][e] = 0.0f;
            const uint32_t* Bh = sm + S_B + (c & 1) * 8192;
            const uint32_t* Bl = Bh + 4096;

            #pragma unroll 4
            for (int ks = 0; ks < 16; ks++) {
                const int k0 = (ks * 8 + tg) ^ xr;
                const int k1 = (ks * 8 + tg + 4) ^ xr;
                uint32_t ah[2][4], al_[2][4], bh[4][2], bl[4][2];
                #pragma unroll
                for (int mt = 0; mt < 2; mt++) {
                    int ba = baseA + mt * 2048;
                    ah[mt][0] = sAh[ba + k0];  ah[mt][1] = sAh[ba + 1024 + k0];
                    ah[mt][2] = sAh[ba + k1];  ah[mt][3] = sAh[ba + 1024 + k1];
                    al_[mt][0] = sAl[ba + k0]; al_[mt][1] = sAl[ba + 1024 + k0];
                    al_[mt][2] = sAl[ba + k1]; al_[mt][3] = sAl[ba + 1024 + k1];
                }
                #pragma unroll
                for (int nt = 0; nt < 4; nt++) {
                    int bb = baseB0 + nt * 1024;
                    bh[nt][0] = Bh[bb + k0]; bh[nt][1] = Bh[bb + k1];
                    bl[nt][0] = Bl[bb + k0]; bl[nt][1] = Bl[bb + k1];
                }
                #pragma unroll
                for (int mt = 0; mt < 2; mt++)
                    #pragma unroll
                    for (int nt = 0; nt < 4; nt++) {
                        mma_f16(acc[mt][nt], ah[mt],  bh[nt]);
                        mma_f16(acc[mt][nt], ah[mt],  bl[nt]);
                        mma_f16(acc[mt][nt], al_[mt], bh[nt]);
                    }
            }
            // fold chunk into running argmin (ascending code order, strict <)
            const int cb = c * NB;
            #pragma unroll
            for (int mt = 0; mt < 2; mt++)
                #pragma unroll
                for (int nt = 0; nt < 4; nt++)
                    #pragma unroll
                    for (int e = 0; e < 4; e++) {
                        int code = cb + nt * 8 + 2 * tg + (e & 1);
                        float dist = Eh[code] - acc[mt][nt][e];
                        int s = mt * 2 + (e >> 1);
                        if (dist < minv[s]) { minv[s] = dist; mini[s] = code; }
                    }
        } else {
            if (c + 1 < NCHK) {            // producer warps: B chunk c+1
                const int code0 = (c + 1) * NB, ptid = tid - 128;
                const int buf = (c + 1) & 1;
                #pragma unroll
                for (int i = 0; i < 16; i++) {
                    int grp = ptid + 128 * i;
                    int hl = grp >> 10, r = grp & 1023;
                    int row = r >> 5, g4 = (r & 31) << 2;
                    const uint32_t* src = (hl ? g_Blo : g_Bhi)
                                        + (size_t)(code0 + row) * 128 + g4;
                    uint32_t dst = sbase + (S_B + buf * 8192 + hl * 4096
                                   + row * 128 + (g4 ^ ((row & 7) << 2))) * 4;
                    cp16(dst, src);
                }
                cp_commit_wait();
            }
        }
        __syncthreads();
    }

    // ---- cross-lane argmin (codes ascend with tg -> ties keep lower idx) ----
    if (wid < 4) {
        #pragma unroll
        for (int o = 1; o <= 2; o <<= 1)
            #pragma unroll
            for (int s = 0; s < 4; s++) {
                float ov = __shfl_xor_sync(0xffffffffu, minv[s], o);
                int   oi = __shfl_xor_sync(0xffffffffu, mini[s], o);
                if (ov < minv[s]) { minv[s] = ov; mini[s] = oi; }
            }
        if (tg == 0) {
            #pragma unroll
            for (int s = 0; s < 4; s++) {
                int row = wid * 32 + s * 8 + g;
                int bi  = mini[s];
                Ri[row] = bi;
                out_idx[tok0 + row] = (float)bi;
                atomicAdd(&g_counts[bi], 1.0f);
            }
        }
    }
    __syncthreads();

    // ---- fused scatter: z reconstructed from smem hi+lo ----
    const int b    = tok0 >> 10;
    const int toff = tok0 & 1023;
    const int tk   = tid & 127;
    const int chh  = tid >> 7;
    const int kk   = Ri[tk];
    const int axr  = (tk & 7) << 2;
    const float* er  = emb + (size_t)kk * D;
    float*       dwr = g_dw + (size_t)kk * D;
    float*       qb  = out_zq + (size_t)b * D * HW + toff;
    const uint32_t* rowH = sAh + tk * 128;
    const uint32_t* rowL = sAl + tk * 128;

    float ls = 0.0f;
    for (int kp = chh * 64; kp < chh * 64 + 64; kp++) {
        uint32_t hv = rowH[kp ^ axr], lv = rowL[kp ^ axr];
        __half2 Hh = *reinterpret_cast<__half2*>(&hv);
        __half2 Ll = *reinterpret_cast<__half2*>(&lv);
        float z0 = __low2float(Hh)  + __low2float(Ll);
        float z1 = __high2float(Hh) + __high2float(Ll);
        int d0 = kp * 2;
        float2 ev = *reinterpret_cast<const float2*>(er + d0);
        float df0 = ev.x - z0, df1 = ev.y - z1;
        qb[(size_t)d0 * HW + tk]       = z0 + df0;
        qb[(size_t)(d0 + 1) * HW + tk] = z1 + df1;
        ls += df0 * df0 + df1 * df1;
        atomicAdd(dwr + d0,     z0);
        atomicAdd(dwr + d0 + 1, z1);
    }
    RED[tid] = ls;
    __syncthreads();
    #pragma unroll
    for (int s = 128; s > 0; s >>= 1) {
        if (tid < s) RED[tid] += RED[tid + s];
        __syncthreads();
    }
    if (tid == 0) atomicAdd(&g_loss, RED[0]);
}

// ---------------- tail kernels (consume + re-zero scratch) ----------------
__global__ void k_cs(const float* __restrict__ ecs, float* __restrict__ out_cs) {
    __shared__ float sred[K];
    int k = threadIdx.x;
    float cr = 0.99f * ecs[k] + 0.01f * g_counts[k];
    g_counts[k] = 0.0f;
    sred[k] = cr;
    __syncthreads();
    #pragma unroll
    for (int s = K / 2; s > 0; s >>= 1) {
        if (k < s) sred[k] += sred[k + s];
        __syncthreads();
    }
    float n = sred[0];
    out_cs[k] = (cr + 1e-5f) / (n + (float)K * 1e-5f) * n;
}

__global__ void k_emb(const float* __restrict__ ema_w, const float* __restrict__ cs,
                      float* __restrict__ out_emaw, float* __restrict__ out_emb) {
    int i = blockIdx.x * blockDim.x + threadIdx.x;
    if (i < K * D) {
        float w = 0.99f * ema_w[i] + 0.01f * g_dw[i];
        g_dw[i] = 0.0f;
        out_emaw[i] = w;
        out_emb[i]  = w / cs[i >> 8];
    }
}

__global__ void k_loss(float* __restrict__ out_loss) {
    if (threadIdx.x == 0) {
        out_loss[0] = 0.25f * g_loss / (float)((size_t)NTOK * D);
        g_loss = 0.0f;
    }
}

extern "C" void kernel_launch(void* const* d_in, const int* in_sizes, int n_in,
                              void* d_out, int out_size) {
    const float* z    = (const float*)d_in[0];
    const float* emb  = (const float*)d_in[1];
    const float* ecs  = (const float*)d_in[2];
    const float* emaw = (const float*)d_in[3];
    float* out = (float*)d_out;

    // output layout: z_q | idx | loss | new_embedding | cs | new_ema_w
    const size_t o_idx  = (size_t)NTOK * D;
    const size_t o_loss = o_idx + NTOK;
    const size_t o_emb  = o_loss + 1;
    const size_t o_cs   = o_emb + (size_t)K * D;
    const size_t o_emaw = o_cs + K;

    cudaFuncSetAttribute(k_argmin, cudaFuncAttributeMaxDynamicSharedMemorySize,
                         SMEM_BYTES);

    k_split_emb <<<K / 8, 256>>>(emb);
    k_split_z   <<<NTOK / 256, 256>>>(z);
    k_argmin    <<<NTOK / TM, 256, SMEM_BYTES>>>(emb, out + o_idx, out);
    k_cs        <<<1, K>>>(ecs, out + o_cs);
    k_emb       <<<(K * D + 255) / 256, 256>>>(emaw, out + o_cs,
                                               out + o_emaw, out + o_emb);
    k_loss      <<<1, 32>>>(out + o_loss);
}

// round 11
// speedup vs baseline: 1.8549x; 1.0053x over previous
#include <cuda_runtime.h>
#include <cuda_fp16.h>
#include <math_constants.h>
#include <cstdint>

// Problem: z [32,256,32,32], embedding [1024,256]
constexpr int D    = 256;
constexpr int K    = 1024;
constexpr int HW   = 1024;
constexpr int NTOK = 32768;
constexpr int TM   = 128;        // tokens per CTA
constexpr int NB   = 32;         // codes per chunk
constexpr int NCHK = K / NB;     // 32

// smem offsets in u32 units
constexpr int S_AHI = 0;         // [128 tok][128 u32] 64KB
constexpr int S_ALO = 16384;
constexpr int S_B   = 32768;     // 2 bufs x (hi 4096 u32 + lo 4096 u32) = 64KB
constexpr int S_EH  = 49152;     // 1024 f32
constexpr int S_RI  = 50176;     // 128 i32
constexpr int S_RED = 50304;     // 256 f32
constexpr int SMEM_U32   = 50560;
constexpr int SMEM_BYTES = SMEM_U32 * 4;   // 202240

// ---- device scratch (static; zero-init, restored by consumers each replay) --
__device__ __align__(16) uint32_t g_Ahi[NTOK * 128];
__device__ __align__(16) uint32_t g_Alo[NTOK * 128];
__device__ __align__(16) uint32_t g_Bhi[K * 128];
__device__ __align__(16) uint32_t g_Blo[K * 128];
__device__ __align__(16) float g_dw[K * D];
__device__ float g_counts[K];
__device__ float g_loss;
__device__ float g_eh[K];                // 0.5*||e_k||^2

// ---------------- helpers ----------------
__device__ __forceinline__ uint32_t smaddr(const void* p) {
    uint32_t a;
    asm("{ .reg .u64 t; cvta.to.shared.u64 t, %1; cvt.u32.u64 %0, t; }"
        : "=r"(a) : "l"(p));
    return a;
}
__device__ __forceinline__ void cp16(uint32_t s, const void* g) {
    asm volatile("cp.async.cg.shared.global [%0], [%1], 16;" :: "r"(s), "l"(g));
}
__device__ __forceinline__ void ldsm4(uint32_t* r, uint32_t addr) {
    asm volatile("ldmatrix.sync.aligned.m8n8.x4.shared.b16 {%0,%1,%2,%3}, [%4];"
        : "=r"(r[0]), "=r"(r[1]), "=r"(r[2]), "=r"(r[3]) : "r"(addr));
}
__device__ __forceinline__ void mma_f16(float* c, const uint32_t* a,
                                        const uint32_t* b) {
    asm volatile("mma.sync.aligned.m16n8k16.row.col.f32.f16.f16.f32 "
        "{%0,%1,%2,%3},{%4,%5,%6,%7},{%8,%9},{%0,%1,%2,%3};"
        : "+f"(c[0]), "+f"(c[1]), "+f"(c[2]), "+f"(c[3])
        : "r"(a[0]), "r"(a[1]), "r"(a[2]), "r"(a[3]), "r"(b[0]), "r"(b[1]));
}
__device__ __forceinline__ uint32_t packsplit(float v0, float v1, uint32_t& lo) {
    __half h0 = __float2half_rn(v0), h1 = __float2half_rn(v1);
    __half l0 = __float2half_rn(v0 - __half2float(h0));
    __half l1 = __float2half_rn(v1 - __half2float(h1));
    __half2 H = __halves2half2(h0, h1), L = __halves2half2(l0, l1);
    lo = *reinterpret_cast<uint32_t*>(&L);
    return *reinterpret_cast<uint32_t*>(&H);
}

// ---------------- split z -> fp16 hi/lo, token-major ----------------
__global__ void k_split_z(const float* __restrict__ z) {
    const int tid  = threadIdx.x;
    const int blk  = blockIdx.x;
    const int b    = blk >> 2;
    const int toff = ((blk & 3) << 8) + tid;
    const int tok  = (b << 10) + toff;
    const float* zp = z + (size_t)b * D * HW + toff;
    uint4* Oh = reinterpret_cast<uint4*>(g_Ahi) + (size_t)tok * 32;
    uint4* Ol = reinterpret_cast<uint4*>(g_Alo) + (size_t)tok * 32;
    for (int g = 0; g < 32; g++) {
        uint32_t hv[4], lv[4];
        #pragma unroll
        for (int q = 0; q < 4; q++) {
            int d0 = (g * 4 + q) * 2;
            float v0 = zp[(size_t)d0 * HW];
            float v1 = zp[(size_t)(d0 + 1) * HW];
            hv[q] = packsplit(v0, v1, lv[q]);
        }
        Oh[g] = make_uint4(hv[0], hv[1], hv[2], hv[3]);
        Ol[g] = make_uint4(lv[0], lv[1], lv[2], lv[3]);
    }
}

// ---------------- split emb -> fp16 hi/lo + 0.5*||e||^2 ----------------
__global__ void k_split_emb(const float* __restrict__ emb) {
    const int wid  = threadIdx.x >> 5, lane = threadIdx.x & 31;
    const int code = blockIdx.x * 8 + wid;
    const float4* r = reinterpret_cast<const float4*>(emb + (size_t)code * D)
                    + lane * 2;
    float4 a = r[0], bq = r[1];
    float v[8] = {a.x, a.y, a.z, a.w, bq.x, bq.y, bq.z, bq.w};
    float s = 0.0f;
    uint32_t hv[4], lv[4];
    #pragma unroll
    for (int q = 0; q < 4; q++) {
        s += v[2*q] * v[2*q] + v[2*q+1] * v[2*q+1];
        hv[q] = packsplit(v[2*q], v[2*q+1], lv[q]);
    }
    reinterpret_cast<uint4*>(g_Bhi)[(size_t)code * 32 + lane] =
        make_uint4(hv[0], hv[1], hv[2], hv[3]);
    reinterpret_cast<uint4*>(g_Blo)[(size_t)code * 32 + lane] =
        make_uint4(lv[0], lv[1], lv[2], lv[3]);
    #pragma unroll
    for (int o = 16; o > 0; o >>= 1) s += __shfl_xor_sync(0xffffffffu, s, o);
    if (lane == 0) g_eh[code] = 0.5f * s;
}

// -------- main: 8-warp HMMA (ldmatrix) 3-product GEMM + argmin + scatter ----
__global__ __launch_bounds__(256, 1)
void k_argmin(const float* __restrict__ emb,
              float* __restrict__ out_idx, float* __restrict__ out_zq) {
    extern __shared__ uint32_t sm[];
    const uint32_t sbase = smaddr(sm);
    float* Eh  = reinterpret_cast<float*>(sm + S_EH);
    int*   Ri  = reinterpret_cast<int*>(sm + S_RI);
    float* RED = reinterpret_cast<float*>(sm + S_RED);

    const int tid  = threadIdx.x;
    const int wid  = tid >> 5;
    const int lane = tid & 31;
    const int tok0 = blockIdx.x * TM;

    // ---- prologue: A (hi/lo, swizzled) + B chunk0 + Eh ----
    #pragma unroll 4
    for (int i = 0; i < 32; i++) {
        int grp = tid + 256 * i;
        int hl = grp >> 12, r = grp & 4095, row = r >> 5, g4 = (r & 31) << 2;
        const uint32_t* src = (hl ? g_Alo : g_Ahi)
                            + (size_t)(tok0 + row) * 128 + g4;
        uint32_t dst = sbase
            + ((hl ? S_ALO : S_AHI) + row * 128 + (g4 ^ ((row & 7) << 2))) * 4;
        cp16(dst, src);
    }
    #pragma unroll
    for (int i = 0; i < 8; i++) {
        int grp = tid + 256 * i;
        int hl = grp >> 10, r = grp & 1023, row = r >> 5, g4 = (r & 31) << 2;
        const uint32_t* src = (hl ? g_Blo : g_Bhi) + (size_t)row * 128 + g4;
        uint32_t dst = sbase
            + (S_B + hl * 4096 + row * 128 + (g4 ^ ((row & 7) << 2))) * 4;
        cp16(dst, src);
    }
    asm volatile("cp.async.commit_group;" ::: "memory");
    for (int i = tid; i < K; i += 256) Eh[i] = g_eh[i];
    asm volatile("cp.async.wait_group 0;" ::: "memory");
    __syncthreads();

    // ldmatrix lane geometry
    const int j  = lane >> 3;       // matrix index 0..3
    const int r8 = lane & 7;        // row within matrix
    const uint32_t ax  = (uint32_t)(r8 << 2);                 // swizzle term
    const uint32_t jjA = (uint32_t)((j >> 1) << 2);           // A k-half
    const uint32_t jbB = (uint32_t)((j & 1) << 2);            // B k-half
    const uint32_t aRow = (uint32_t)((wid * 16 + (j & 1) * 8 + r8) * 128);
    const uint32_t bRow0 = (uint32_t)(((j >> 1) * 8 + r8) * 128);        // tiles 0,1
    const uint32_t bRow1 = bRow0 + 16 * 128;                             // tiles 2,3

    float minv[2] = {CUDART_INF_F, CUDART_INF_F};
    int   mini[2] = {0, 0};

    for (int c = 0; c < NCHK; c++) {
        if (c + 1 < NCHK) {          // every warp copies its slice of chunk c+1
            const int code0 = (c + 1) * NB;
            const uint32_t bufo = (uint32_t)(S_B + ((c + 1) & 1) * 8192);
            #pragma unroll
            for (int i = 0; i < 8; i++) {
                int grp = tid + 256 * i;
                int hl = grp >> 10, rr = grp & 1023;
                int row = rr >> 5, g4 = (rr & 31) << 2;
                const uint32_t* src = (hl ? g_Blo : g_Bhi)
                                    + (size_t)(code0 + row) * 128 + g4;
                uint32_t dst = sbase + (bufo + hl * 4096
                               + row * 128 + (g4 ^ ((row & 7) << 2))) * 4;
                cp16(dst, src);
            }
            asm volatile("cp.async.commit_group;" ::: "memory");
        }

        // ---- compute chunk c ----
        const uint32_t bB = sbase + (uint32_t)(S_B + (c & 1) * 8192) * 4;
        const uint32_t aH = sbase + (uint32_t)S_AHI * 4;
        const uint32_t aL = sbase + (uint32_t)S_ALO * 4;
        float acc[4][4];
        #pragma unroll
        for (int nt = 0; nt < 4; nt++)
            #pragma unroll
            for (int e = 0; e < 4; e++) acc[nt][e] = 0.0f;

        #pragma unroll 4
        for (int ks = 0; ks < 16; ks++) {
            const uint32_t tA = ((uint32_t)(ks * 8) + jjA) ^ ax;
            const uint32_t tB = ((uint32_t)(ks * 8) + jbB) ^ ax;
            uint32_t ah[4], al_[4], b01h[4], b23h[4], b01l[4], b23l[4];
            ldsm4(ah,   aH + (aRow + tA) * 4);
            ldsm4(al_,  aL + (aRow + tA) * 4);
            ldsm4(b01h, bB + (bRow0 + tB) * 4);
            ldsm4(b23h, bB + (bRow1 + tB) * 4);
            ldsm4(b01l, bB + 16384 + (bRow0 + tB) * 4);
            ldsm4(b23l, bB + 16384 + (bRow1 + tB) * 4);
            #pragma unroll
            for (int nt = 0; nt < 4; nt++) {
                const uint32_t* bh = (nt < 2) ? (b01h + 2 * nt) : (b23h + 2 * (nt - 2));
                const uint32_t* bl = (nt < 2) ? (b01l + 2 * nt) : (b23l + 2 * (nt - 2));
                mma_f16(acc[nt], ah,  bh);
                mma_f16(acc[nt], ah,  bl);
                mma_f16(acc[nt], al_, bh);
            }
        }

        // fold chunk into running argmin (ascending code order, strict <)
        const int cb = c * NB;
        #pragma unroll
        for (int nt = 0; nt < 4; nt++)
            #pragma unroll
            for (int e = 0; e < 4; e++) {
                int code = cb + nt * 8 + 2 * (lane & 3) + (e & 1);
                float dist = Eh[code] - acc[nt][e];
                int s = e >> 1;
                if (dist < minv[s]) { minv[s] = dist; mini[s] = code; }
            }

        if (c + 1 < NCHK)
            asm volatile("cp.async.wait_group 0;" ::: "memory");
        __syncthreads();
    }

    // ---- cross-lane argmin within quads (rows l>>2, l>>2+8) ----
    #pragma unroll
    for (int o = 1; o <= 2; o <<= 1)
        #pragma unroll
        for (int s = 0; s < 2; s++) {
            float ov = __shfl_xor_sync(0xffffffffu, minv[s], o);
            int   oi = __shfl_xor_sync(0xffffffffu, mini[s], o);
            if (ov < minv[s] || (ov == minv[s] && oi < mini[s])) {
                minv[s] = ov; mini[s] = oi;
            }
        }
    if ((lane & 3) == 0) {
        #pragma unroll
        for (int s = 0; s < 2; s++) {
            int row = wid * 16 + s * 8 + (lane >> 2);
            int bi  = mini[s];
            Ri[row] = bi;
            out_idx[tok0 + row] = (float)bi;
            atomicAdd(&g_counts[bi], 1.0f);
        }
    }
    __syncthreads();

    // ---- fused scatter: z reconstructed from smem hi+lo ----
    const int b    = tok0 >> 10;
    const int toff = tok0 & 1023;
    const int tk   = tid & 127;
    const int chh  = tid >> 7;
    const int kk   = Ri[tk];
    const int axr  = (tk & 7) << 2;
    const float* er  = emb + (size_t)kk * D;
    float*       dwr = g_dw + (size_t)kk * D;
    float*       qb  = out_zq + (size_t)b * D * HW + toff;
    const uint32_t* rowH = sm + S_AHI + tk * 128;
    const uint32_t* rowL = sm + S_ALO + tk * 128;

    float ls = 0.0f;
    for (int kp = chh * 64; kp < chh * 64 + 64; kp++) {
        uint32_t hv = rowH[kp ^ axr], lv = rowL[kp ^ axr];
        __half2 Hh = *reinterpret_cast<__half2*>(&hv);
        __half2 Ll = *reinterpret_cast<__half2*>(&lv);
        float z0 = __low2float(Hh)  + __low2float(Ll);
        float z1 = __high2float(Hh) + __high2float(Ll);
        int d0 = kp * 2;
        float2 ev = *reinterpret_cast<const float2*>(er + d0);
        float df0 = ev.x - z0, df1 = ev.y - z1;
        qb[(size_t)d0 * HW + tk]       = z0 + df0;
        qb[(size_t)(d0 + 1) * HW + tk] = z1 + df1;
        ls += df0 * df0 + df1 * df1;
        atomicAdd(dwr + d0,     z0);
        atomicAdd(dwr + d0 + 1, z1);
    }
    RED[tid] = ls;
    __syncthreads();
    #pragma unroll
    for (int s = 128; s > 0; s >>= 1) {
        if (tid < s) RED[tid] += RED[tid + s];
        __syncthreads();
    }
    if (tid == 0) atomicAdd(&g_loss, RED[0]);
}

// ---------------- tail kernels (consume + re-zero scratch) ----------------
__global__ void k_cs(const float* __restrict__ ecs, float* __restrict__ out_cs) {
    __shared__ float part[32];
    int k = threadIdx.x, lane = k & 31, w = k >> 5;
    float cr = 0.99f * ecs[k] + 0.01f * g_counts[k];
    g_counts[k] = 0.0f;
    float s = cr;
    #pragma unroll
    for (int o = 16; o > 0; o >>= 1) s += __shfl_xor_sync(0xffffffffu, s, o);
    if (lane == 0) part[w] = s;
    __syncthreads();
    if (w == 0) {
        float t = part[lane];
        #pragma unroll
        for (int o = 16; o > 0; o >>= 1) t += __shfl_xor_sync(0xffffffffu, t, o);
        if (lane == 0) part[0] = t;
    }
    __syncthreads();
    float n = part[0];
    out_cs[k] = (cr + 1e-5f) / (n + (float)K * 1e-5f) * n;
}

// NOTE: out_emaw/out_emb sit at odd float offsets in d_out -> scalar stores only.
__global__ void k_emb(const float* __restrict__ ema_w, const float* __restrict__ cs,
                      float* __restrict__ out_emaw, float* __restrict__ out_emb) {
    int i4 = (blockIdx.x * blockDim.x + threadIdx.x) * 4;
    if (i4 < K * D) {
        float4 w4 = *reinterpret_cast<const float4*>(ema_w + i4);
        float4 d4 = *reinterpret_cast<const float4*>(g_dw + i4);
        *reinterpret_cast<float4*>(g_dw + i4) = make_float4(0.f, 0.f, 0.f, 0.f);
        float inv = 1.0f / cs[i4 >> 8];
        float w0 = 0.99f * w4.x + 0.01f * d4.x;
        float w1 = 0.99f * w4.y + 0.01f * d4.y;
        float w2 = 0.99f * w4.z + 0.01f * d4.z;
        float w3 = 0.99f * w4.w + 0.01f * d4.w;
        out_emaw[i4 + 0] = w0;  out_emb[i4 + 0] = w0 * inv;
        out_emaw[i4 + 1] = w1;  out_emb[i4 + 1] = w1 * inv;
        out_emaw[i4 + 2] = w2;  out_emb[i4 + 2] = w2 * inv;
        out_emaw[i4 + 3] = w3;  out_emb[i4 + 3] = w3 * inv;
    }
}

__global__ void k_loss(float* __restrict__ out_loss) {
    if (threadIdx.x == 0) {
        out_loss[0] = 0.25f * g_loss / (float)((size_t)NTOK * D);
        g_loss = 0.0f;
    }
}

extern "C" void kernel_launch(void* const* d_in, const int* in_sizes, int n_in,
                              void* d_out, int out_size) {
    const float* z    = (const float*)d_in[0];
    const float* emb  = (const float*)d_in[1];
    const float* ecs  = (const float*)d_in[2];
    const float* emaw = (const float*)d_in[3];
    float* out = (float*)d_out;

    // output layout: z_q | idx | loss | new_embedding | cs | new_ema_w
    const size_t o_idx  = (size_t)NTOK * D;
    const size_t o_loss = o_idx + NTOK;
    const size_t o_emb  = o_loss + 1;
    const size_t o_cs   = o_emb + (size_t)K * D;
    const size_t o_emaw = o_cs + K;

    cudaFuncSetAttribute(k_argmin, cudaFuncAttributeMaxDynamicSharedMemorySize,
                         SMEM_BYTES);

    k_split_emb <<<K / 8, 256>>>(emb);
    k_split_z   <<<NTOK / 256, 256>>>(z);
    k_argmin    <<<NTOK / TM, 256, SMEM_BYTES>>>(emb, out + o_idx, out);
    k_cs        <<<1, K>>>(ecs, out + o_cs);
    k_emb       <<<K * D / 1024, 256>>>(emaw, out + o_cs,
                                        out + o_emaw, out + o_emb);
    k_loss      <<<1, 32>>>(out + o_loss);
}